// round 4
// baseline (speedup 1.0000x reference)
#include <cuda_runtime.h>

#define NR      116
#define RSTRIDE 128            // padded row length in float2 (1024 B rows)
#define NT      224            // threads per block
#define GRID    152            // one CTA per SM (GB300 = 152 SMs)
#define NTOT    (16*3*512*512) // 12,582,912
#define NV4     (NTOT/4)       // 3,145,728

// Per-block partial (sum, count) per region. No atomics anywhere -> deterministic.
__device__ float2 g_part[GRID * NR];

// Accumulate one scalar element into this thread's private histogram row.
__device__ __forceinline__ void acc1(float2* myrow, float x, float y, int r)
{
    float2 v = myrow[r];
    v.x += fabsf(x - y);
    v.y += 1.0f;
    myrow[r] = v;
}

__device__ __forceinline__ void acc4(float2* myrow, float4 a, float4 b, int4 m)
{
    acc1(myrow, a.x, b.x, m.x);
    acc1(myrow, a.y, b.y, m.y);
    acc1(myrow, a.z, b.z, m.z);
    acc1(myrow, a.w, b.w, m.w);
}

__global__ void __launch_bounds__(NT, 1)
hist_kernel(const float* __restrict__ realp,
            const float* __restrict__ fakep,
            const int*   __restrict__ rmapp)
{
    extern __shared__ float2 hist[];   // [NT][RSTRIDE]
    const int tid = threadIdx.x;

    // Zero all private histograms (linear, conflict-free).
    for (int k = tid; k < NT * RSTRIDE; k += NT)
        hist[k] = make_float2(0.f, 0.f);
    __syncthreads();

    float2* myrow = hist + tid * RSTRIDE;

    const float4* __restrict__ R = (const float4*)realp;
    const float4* __restrict__ F = (const float4*)fakep;
    const int4*   __restrict__ M = (const int4*)rmapp;

    const int T = GRID * NT;
    int i = blockIdx.x * NT + tid;

    // Main loop: 4x unrolled grid-stride over vec4 elements (12 x 16B loads
    // front-batched per iteration for memory-level parallelism).
    for (; i < NV4 - 3 * T; i += 4 * T) {
        float4 a0 = R[i];         float4 b0 = F[i];         int4 m0 = M[i];
        float4 a1 = R[i + T];     float4 b1 = F[i + T];     int4 m1 = M[i + T];
        float4 a2 = R[i + 2*T];   float4 b2 = F[i + 2*T];   int4 m2 = M[i + 2*T];
        float4 a3 = R[i + 3*T];   float4 b3 = F[i + 3*T];   int4 m3 = M[i + 3*T];
        acc4(myrow, a0, b0, m0);
        acc4(myrow, a1, b1, m1);
        acc4(myrow, a2, b2, m2);
        acc4(myrow, a3, b3, m3);
    }
    for (; i < NV4; i += T) {
        float4 a = R[i]; float4 b = F[i]; int4 m = M[i];
        acc4(myrow, a, b, m);
    }

    __syncthreads();

    // Block reduction: thread r sums region r across all NT private rows.
    // Column access: word index = 256*row + 2*r -> distinct banks across lanes.
    if (tid < NR) {
        float s = 0.f, c = 0.f;
        for (int r = 0; r < NT; r++) {
            float2 v = hist[r * RSTRIDE + tid];
            s += v.x;
            c += v.y;
        }
        g_part[blockIdx.x * NR + tid] = make_float2(s, c);
    }
}

__global__ void finalize_kernel(float* __restrict__ out)
{
    __shared__ float sh_m[NR];
    __shared__ float sh_s[NR];
    const int tid = threadIdx.x;

    if (tid < NR) {
        double s = 0.0, c = 0.0;
        for (int b = 0; b < GRID; b++) {
            float2 v = g_part[b * NR + tid];
            s += (double)v.x;
            c += (double)v.y;
        }
        sh_s[tid] = (float)s;
        sh_m[tid] = (float)(s / (c + 1e-6));
    }
    __syncthreads();

    if (tid == 0) {
        float mx = 0.f;   // running max starts at 0 (matches max(0, max_r m_r))
        for (int r = 0; r < NR; r++)
            mx = fmaxf(mx, sh_m[r]);
        double inv = 1e-3 / ((double)mx + 1e-6);
        double tot = 0.0;
        for (int r = 0; r < NR; r++)
            tot += (double)sh_s[r] * (1.0 + inv * (double)sh_m[r]);
        out[0] = (float)(tot / (double)NTOT);
    }
}

extern "C" void kernel_launch(void* const* d_in, const int* in_sizes, int n_in,
                              void* d_out, int out_size)
{
    const float* realp = (const float*)d_in[0];
    const float* fakep = (const float*)d_in[1];
    const int*   rmapp = (const int*)d_in[2];

    // Opt-in to >48KB dynamic shared memory (idempotent; first call happens on
    // the non-captured correctness run, so capture sees it already applied).
    cudaFuncSetAttribute(hist_kernel,
                         cudaFuncAttributeMaxDynamicSharedMemorySize,
                         NT * RSTRIDE * (int)sizeof(float2));

    hist_kernel<<<GRID, NT, NT * RSTRIDE * sizeof(float2)>>>(realp, fakep, rmapp);
    finalize_kernel<<<1, 128>>>((float*)d_out);
}

// round 6
// speedup vs baseline: 1.5514x; 1.5514x over previous
#include <cuda_runtime.h>

#define NR      116
#define RSTRIDE 128            // padded row length in float2 (1024 B rows)
#define NT      224            // threads per block
#define GRID    152            // one CTA per SM (GB300 = 152 SMs)
#define NTOT    (16*3*512*512) // 12,582,912
#define NV4     (NTOT/4)       // 3,145,728
#define FB      8              // finalize: groups per region

// Per-block partial (sum, count) per region. No atomics anywhere -> deterministic.
__device__ float2 g_part[GRID * NR];

// Accumulate one scalar element into this thread's private histogram row.
__device__ __forceinline__ void acc1(float2* myrow, float x, float y, int r)
{
    float2 v = myrow[r];
    v.x += fabsf(x - y);
    v.y += 1.0f;
    myrow[r] = v;
}

__device__ __forceinline__ void acc4(float2* myrow, float4 a, float4 b, int4 m)
{
    acc1(myrow, a.x, b.x, m.x);
    acc1(myrow, a.y, b.y, m.y);
    acc1(myrow, a.z, b.z, m.z);
    acc1(myrow, a.w, b.w, m.w);
}

__global__ void __launch_bounds__(NT, 1)
hist_kernel(const float* __restrict__ realp,
            const float* __restrict__ fakep,
            const int*   __restrict__ rmapp)
{
    extern __shared__ float2 hist[];   // [NT][RSTRIDE]
    const int tid = threadIdx.x;

    // Zero all private histograms (linear, conflict-free).
    for (int k = tid; k < NT * RSTRIDE; k += NT)
        hist[k] = make_float2(0.f, 0.f);
    __syncthreads();

    float2* myrow = hist + tid * RSTRIDE;

    const float4* __restrict__ R = (const float4*)realp;
    const float4* __restrict__ F = (const float4*)fakep;
    const int4*   __restrict__ M = (const int4*)rmapp;

    const int T = GRID * NT;
    int i = blockIdx.x * NT + tid;

    // Main loop: 4x unrolled grid-stride over vec4 elements (12 x 16B loads
    // front-batched per iteration for memory-level parallelism).
    for (; i < NV4 - 3 * T; i += 4 * T) {
        float4 a0 = R[i];         float4 b0 = F[i];         int4 m0 = M[i];
        float4 a1 = R[i + T];     float4 b1 = F[i + T];     int4 m1 = M[i + T];
        float4 a2 = R[i + 2*T];   float4 b2 = F[i + 2*T];   int4 m2 = M[i + 2*T];
        float4 a3 = R[i + 3*T];   float4 b3 = F[i + 3*T];   int4 m3 = M[i + 3*T];
        acc4(myrow, a0, b0, m0);
        acc4(myrow, a1, b1, m1);
        acc4(myrow, a2, b2, m2);
        acc4(myrow, a3, b3, m3);
    }
    for (; i < NV4; i += T) {
        float4 a = R[i]; float4 b = F[i]; int4 m = M[i];
        acc4(myrow, a, b, m);
    }

    __syncthreads();

    // Block reduction: thread r sums region r across all NT private rows.
    // Column access: word index = 256*row + 2*r -> distinct banks across lanes.
    if (tid < NR) {
        float s = 0.f, c = 0.f;
        for (int r = 0; r < NT; r++) {
            float2 v = hist[r * RSTRIDE + tid];
            s += v.x;
            c += v.y;
        }
        g_part[blockIdx.x * NR + tid] = make_float2(s, c);
    }
}

// Parallel finalize: 116 regions x 8 groups sum the 152 block-partials with
// high MLP, then fp32 shared/warp reductions for mean, max, weighted total.
__global__ void __launch_bounds__(1024, 1)
finalize_kernel(float* __restrict__ out)
{
    __shared__ float2 part[NR][FB];
    __shared__ float  sh_s[NR];
    __shared__ float  sh_m[NR];
    __shared__ float  sh_max;

    const int t = threadIdx.x;

    if (t < NR * FB) {
        const int r = t / FB;
        const int g = t % FB;
        float s = 0.f, c = 0.f;
        #pragma unroll
        for (int b = g; b < GRID; b += FB) {   // 19 independent loads
            float2 v = g_part[b * NR + r];
            s += v.x;
            c += v.y;
        }
        part[r][g] = make_float2(s, c);
    }
    __syncthreads();

    if (t < NR) {
        float s = 0.f, c = 0.f;
        #pragma unroll
        for (int g = 0; g < FB; g++) {
            float2 v = part[t][g];
            s += v.x;
            c += v.y;
        }
        sh_s[t] = s;
        sh_m[t] = s / (c + 1e-6f);
    }
    __syncthreads();

    if (t < 32) {
        float mx = 0.f;   // running max starts at 0 (matches max(0, max_r m_r))
        for (int r = t; r < NR; r += 32)
            mx = fmaxf(mx, sh_m[r]);
        #pragma unroll
        for (int o = 16; o; o >>= 1)
            mx = fmaxf(mx, __shfl_xor_sync(0xffffffffu, mx, o));
        if (t == 0) sh_max = mx;
    }
    __syncthreads();

    if (t < 32) {
        const float inv = 1e-3f / (sh_max + 1e-6f);
        float tot = 0.f;
        for (int r = t; r < NR; r += 32)
            tot += sh_s[r] * (1.0f + inv * sh_m[r]);
        #pragma unroll
        for (int o = 16; o; o >>= 1)
            tot += __shfl_xor_sync(0xffffffffu, tot, o);
        if (t == 0) out[0] = tot / (float)NTOT;
    }
}

extern "C" void kernel_launch(void* const* d_in, const int* in_sizes, int n_in,
                              void* d_out, int out_size)
{
    const float* realp = (const float*)d_in[0];
    const float* fakep = (const float*)d_in[1];
    const int*   rmapp = (const int*)d_in[2];

    // Opt-in to >48KB dynamic shared memory (idempotent; first call happens on
    // the non-captured correctness run, so capture sees it already applied).
    cudaFuncSetAttribute(hist_kernel,
                         cudaFuncAttributeMaxDynamicSharedMemorySize,
                         NT * RSTRIDE * (int)sizeof(float2));

    hist_kernel<<<GRID, NT, NT * RSTRIDE * sizeof(float2)>>>(realp, fakep, rmapp);
    finalize_kernel<<<1, 1024>>>((float*)d_out);
}

// round 7
// speedup vs baseline: 1.6244x; 1.0470x over previous
#include <cuda_runtime.h>

#define NR      116
#define NT      224            // threads per block (7 warps)
#define NW      7              // warps per block
#define GRID    152            // one CTA per SM (GB300 = 152 SMs)
#define NTOT    (16*3*512*512) // 12,582,912
#define NV4     (NTOT/4)       // 3,145,728

// Per-block partial (sum, count) per region, plus a ticket for last-block
// finalize. No data atomics -> bitwise deterministic result.
__device__ float2   g_part[GRID * NR];
__device__ unsigned g_ticket = 0;   // reset to 0 by the finalizing block

// Accumulate one scalar element. Layout hist[region][thread]: bank index
// depends only on tid (448*r = 0 mod 32 banks) -> conflict-free LDS/STS.64.
__device__ __forceinline__ void acc1(float2* slot0, float x, float y, int r)
{
    float2* p = slot0 + r * NT;
    float2 v = *p;
    v.x += fabsf(x - y);
    v.y += 1.0f;
    *p = v;
}

__device__ __forceinline__ void acc4(float2* slot0, float4 a, float4 b, int4 m)
{
    acc1(slot0, a.x, b.x, m.x);
    acc1(slot0, a.y, b.y, m.y);
    acc1(slot0, a.z, b.z, m.z);
    acc1(slot0, a.w, b.w, m.w);
}

__global__ void __launch_bounds__(NT, 1)
fused_kernel(const float* __restrict__ realp,
             const float* __restrict__ fakep,
             const int*   __restrict__ rmapp,
             float* __restrict__ out)
{
    extern __shared__ float2 hist[];   // [NR][NT] = 203 KB
    const int tid  = threadIdx.x;
    const int warp = tid >> 5;
    const int lane = tid & 31;

    // Zero private histograms (linear, conflict-free, vectorized).
    {
        float4* h4 = (float4*)hist;
        const int n4 = NR * NT / 2;          // float2 pairs as float4
        for (int k = tid; k < n4; k += NT)
            h4[k] = make_float4(0.f, 0.f, 0.f, 0.f);
    }
    __syncthreads();

    float2* slot0 = hist + tid;              // this thread's column

    const float4* __restrict__ R = (const float4*)realp;
    const float4* __restrict__ F = (const float4*)fakep;
    const int4*   __restrict__ M = (const int4*)rmapp;

    const int T = GRID * NT;
    int i = blockIdx.x * NT + tid;

    // 4x unrolled grid-stride over vec4 elements; 12 independent 16B loads
    // per iteration are hoisted for MLP.
    for (; i < NV4 - 3 * T; i += 4 * T) {
        float4 a0 = R[i];         float4 b0 = F[i];         int4 m0 = M[i];
        float4 a1 = R[i + T];     float4 b1 = F[i + T];     int4 m1 = M[i + T];
        float4 a2 = R[i + 2*T];   float4 b2 = F[i + 2*T];   int4 m2 = M[i + 2*T];
        float4 a3 = R[i + 3*T];   float4 b3 = F[i + 3*T];   int4 m3 = M[i + 3*T];
        acc4(slot0, a0, b0, m0);
        acc4(slot0, a1, b1, m1);
        acc4(slot0, a2, b2, m2);
        acc4(slot0, a3, b3, m3);
    }
    for (; i < NV4; i += T) {
        float4 a = R[i]; float4 b = F[i]; int4 m = M[i];
        acc4(slot0, a, b, m);
    }

    __syncthreads();

    // Block reduction: warp w handles regions w, w+7, ... Lanes stride the
    // thread axis (bank = 2*lane -> conflict-free), then shfl-combine.
    for (int r = warp; r < NR; r += NW) {
        float s = 0.f, c = 0.f;
        #pragma unroll
        for (int k = 0; k < NT / 32; k++) {
            float2 v = hist[r * NT + lane + k * 32];
            s += v.x;
            c += v.y;
        }
        #pragma unroll
        for (int o = 16; o; o >>= 1) {
            s += __shfl_xor_sync(0xffffffffu, s, o);
            c += __shfl_xor_sync(0xffffffffu, c, o);
        }
        if (lane == 0)
            g_part[blockIdx.x * NR + r] = make_float2(s, c);
    }

    // ---- last-block finalize (threadfence-reduction pattern) ----
    __threadfence();            // publish this block's g_part writes
    __syncthreads();

    __shared__ unsigned is_last;
    if (tid == 0)
        is_last = (atomicAdd(&g_ticket, 1u) == GRID - 1) ? 1u : 0u;
    __syncthreads();
    if (!is_last)
        return;
    __threadfence();            // acquire side: see all blocks' partials

    // Reuse the (now free) histogram smem.
    float* sh_s = (float*)hist;
    float* sh_m = sh_s + NR;
    __shared__ float sh_max;

    if (tid < NR) {
        float s = 0.f, c = 0.f;
        #pragma unroll 8
        for (int b = 0; b < GRID; b++) {      // independent loads -> MLP
            float2 v = g_part[b * NR + tid];
            s += v.x;
            c += v.y;
        }
        sh_s[tid] = s;
        sh_m[tid] = s / (c + 1e-6f);
    }
    __syncthreads();

    if (tid < 32) {
        float mx = 0.f;   // running max starts at 0 (matches max(0, max_r m_r))
        for (int r = tid; r < NR; r += 32)
            mx = fmaxf(mx, sh_m[r]);
        #pragma unroll
        for (int o = 16; o; o >>= 1)
            mx = fmaxf(mx, __shfl_xor_sync(0xffffffffu, mx, o));
        if (tid == 0) sh_max = mx;
    }
    __syncthreads();

    if (tid < 32) {
        const float inv = 1e-3f / (sh_max + 1e-6f);
        float tot = 0.f;
        for (int r = tid; r < NR; r += 32)
            tot += sh_s[r] * (1.0f + inv * sh_m[r]);
        #pragma unroll
        for (int o = 16; o; o >>= 1)
            tot += __shfl_xor_sync(0xffffffffu, tot, o);
        if (tid == 0) {
            out[0] = tot / (float)NTOT;
            g_ticket = 0;       // reset for next (deterministic) replay
        }
    }
}

extern "C" void kernel_launch(void* const* d_in, const int* in_sizes, int n_in,
                              void* d_out, int out_size)
{
    const float* realp = (const float*)d_in[0];
    const float* fakep = (const float*)d_in[1];
    const int*   rmapp = (const int*)d_in[2];

    // Opt-in to >48KB dynamic shared memory (idempotent; first call happens on
    // the non-captured correctness run, so capture sees it already applied).
    cudaFuncSetAttribute(fused_kernel,
                         cudaFuncAttributeMaxDynamicSharedMemorySize,
                         NR * NT * (int)sizeof(float2));

    fused_kernel<<<GRID, NT, NR * NT * sizeof(float2)>>>(realp, fakep, rmapp,
                                                         (float*)d_out);
}

// round 9
// speedup vs baseline: 1.8242x; 1.1230x over previous
#include <cuda_runtime.h>

#define NR      116
#define NT      224            // threads per block (7 warps)
#define NW      7              // warps per block
#define GRID    152            // one CTA per SM (GB300 = 152 SMs)
#define NTOT    (16*3*512*512) // 12,582,912
#define NV4     (NTOT/4)       // 3,145,728

// Per-block partial (sum, count) per region, plus a ticket for last-block
// finalize. No data atomics -> bitwise deterministic result.
__device__ float2   g_part[GRID * NR];
__device__ unsigned g_ticket = 0;   // reset to 0 by the finalizing block

// Accumulate one scalar element. Layout hist[region][thread]: bank index
// depends only on tid (448*r = 0 mod 32 banks) -> conflict-free LDS/STS.64.
__device__ __forceinline__ void acc1(float2* slot0, float x, float y, int r)
{
    float2* p = slot0 + r * NT;
    float2 v = *p;
    v.x += fabsf(x - y);
    v.y += 1.0f;
    *p = v;
}

__device__ __forceinline__ void acc4(float2* slot0, float4 a, float4 b, int4 m)
{
    acc1(slot0, a.x, b.x, m.x);
    acc1(slot0, a.y, b.y, m.y);
    acc1(slot0, a.z, b.z, m.z);
    acc1(slot0, a.w, b.w, m.w);
}

__global__ void __launch_bounds__(NT, 1)
fused_kernel(const float* __restrict__ realp,
             const float* __restrict__ fakep,
             const int*   __restrict__ rmapp,
             float* __restrict__ out)
{
    extern __shared__ float2 hist[];   // [NR][NT] = 203 KB
    const int tid  = threadIdx.x;
    const int warp = tid >> 5;
    const int lane = tid & 31;

    // Zero private histograms (linear, conflict-free, vectorized).
    {
        float4* h4 = (float4*)hist;
        const int n4 = NR * NT / 2;          // float2 pairs as float4
        for (int k = tid; k < n4; k += NT)
            h4[k] = make_float4(0.f, 0.f, 0.f, 0.f);
    }
    __syncthreads();

    float2* slot0 = hist + tid;              // this thread's column

    const float4* __restrict__ R = (const float4*)realp;
    const float4* __restrict__ F = (const float4*)fakep;
    const int4*   __restrict__ M = (const int4*)rmapp;

    const int T = GRID * NT;
    int p = blockIdx.x * NT + tid;

    // ---- software-pipelined main loop (prefetch distance = 1 block of 4) ----
    float4 a0, a1, a2, a3, b0, b1, b2, b3;
    int4   m0, m1, m2, m3;

    const bool have = (p < NV4 - 3 * T);
    if (have) {
        a0 = __ldcs(&R[p]);        b0 = __ldcs(&F[p]);        m0 = __ldcs(&M[p]);
        a1 = __ldcs(&R[p + T]);    b1 = __ldcs(&F[p + T]);    m1 = __ldcs(&M[p + T]);
        a2 = __ldcs(&R[p + 2*T]);  b2 = __ldcs(&F[p + 2*T]);  m2 = __ldcs(&M[p + 2*T]);
        a3 = __ldcs(&R[p + 3*T]);  b3 = __ldcs(&F[p + 3*T]);  m3 = __ldcs(&M[p + 3*T]);
        p += 4 * T;
    }

    #pragma unroll 1
    while (p < NV4 - 3 * T) {
        // Prefetch the NEXT block before accumulating the current one, so the
        // 12 LDGs are in flight during the ~560-cycle smem chain below.
        float4 na0 = __ldcs(&R[p]);        float4 nb0 = __ldcs(&F[p]);        int4 nm0 = __ldcs(&M[p]);
        float4 na1 = __ldcs(&R[p + T]);    float4 nb1 = __ldcs(&F[p + T]);    int4 nm1 = __ldcs(&M[p + T]);
        float4 na2 = __ldcs(&R[p + 2*T]);  float4 nb2 = __ldcs(&F[p + 2*T]);  int4 nm2 = __ldcs(&M[p + 2*T]);
        float4 na3 = __ldcs(&R[p + 3*T]);  float4 nb3 = __ldcs(&F[p + 3*T]);  int4 nm3 = __ldcs(&M[p + 3*T]);

        acc4(slot0, a0, b0, m0);
        acc4(slot0, a1, b1, m1);
        acc4(slot0, a2, b2, m2);
        acc4(slot0, a3, b3, m3);

        a0 = na0; b0 = nb0; m0 = nm0;
        a1 = na1; b1 = nb1; m1 = nm1;
        a2 = na2; b2 = nb2; m2 = nm2;
        a3 = na3; b3 = nb3; m3 = nm3;
        p += 4 * T;
    }
    if (have) {
        acc4(slot0, a0, b0, m0);
        acc4(slot0, a1, b1, m1);
        acc4(slot0, a2, b2, m2);
        acc4(slot0, a3, b3, m3);
    }

    // Scalar-vec4 tail.
    for (; p < NV4; p += T) {
        float4 a = __ldcs(&R[p]); float4 b = __ldcs(&F[p]); int4 m = __ldcs(&M[p]);
        acc4(slot0, a, b, m);
    }

    __syncthreads();

    // Block reduction: warp w handles regions w, w+7, ... Lanes stride the
    // thread axis (bank = 2*lane -> conflict-free), then shfl-combine.
    for (int r = warp; r < NR; r += NW) {
        float s = 0.f, c = 0.f;
        #pragma unroll
        for (int k = 0; k < NT / 32; k++) {
            float2 v = hist[r * NT + lane + k * 32];
            s += v.x;
            c += v.y;
        }
        #pragma unroll
        for (int o = 16; o; o >>= 1) {
            s += __shfl_xor_sync(0xffffffffu, s, o);
            c += __shfl_xor_sync(0xffffffffu, c, o);
        }
        if (lane == 0)
            g_part[blockIdx.x * NR + r] = make_float2(s, c);
    }

    // ---- last-block finalize (threadfence-reduction pattern) ----
    __threadfence();            // publish this block's g_part writes
    __syncthreads();

    __shared__ unsigned is_last;
    if (tid == 0)
        is_last = (atomicAdd(&g_ticket, 1u) == GRID - 1) ? 1u : 0u;
    __syncthreads();
    if (!is_last)
        return;
    __threadfence();            // acquire side: see all blocks' partials

    // Reuse the (now free) histogram smem.
    float* sh_s = (float*)hist;
    float* sh_m = sh_s + NR;
    __shared__ float sh_max;

    if (tid < NR) {
        float s = 0.f, c = 0.f;
        #pragma unroll 8
        for (int b = 0; b < GRID; b++) {      // independent loads -> MLP
            float2 v = g_part[b * NR + tid];
            s += v.x;
            c += v.y;
        }
        sh_s[tid] = s;
        sh_m[tid] = s / (c + 1e-6f);
    }
    __syncthreads();

    if (tid < 32) {
        float mx = 0.f;   // running max starts at 0 (matches max(0, max_r m_r))
        for (int r = tid; r < NR; r += 32)
            mx = fmaxf(mx, sh_m[r]);
        #pragma unroll
        for (int o = 16; o; o >>= 1)
            mx = fmaxf(mx, __shfl_xor_sync(0xffffffffu, mx, o));
        if (tid == 0) sh_max = mx;
    }
    __syncthreads();

    if (tid < 32) {
        const float inv = 1e-3f / (sh_max + 1e-6f);
        float tot = 0.f;
        for (int r = tid; r < NR; r += 32)
            tot += sh_s[r] * (1.0f + inv * sh_m[r]);
        #pragma unroll
        for (int o = 16; o; o >>= 1)
            tot += __shfl_xor_sync(0xffffffffu, tot, o);
        if (tid == 0) {
            out[0] = tot / (float)NTOT;
            g_ticket = 0;       // reset for next (deterministic) replay
        }
    }
}

extern "C" void kernel_launch(void* const* d_in, const int* in_sizes, int n_in,
                              void* d_out, int out_size)
{
    const float* realp = (const float*)d_in[0];
    const float* fakep = (const float*)d_in[1];
    const int*   rmapp = (const int*)d_in[2];

    // Opt-in to >48KB dynamic shared memory (idempotent; first call happens on
    // the non-captured correctness run, so capture sees it already applied).
    cudaFuncSetAttribute(fused_kernel,
                         cudaFuncAttributeMaxDynamicSharedMemorySize,
                         NR * NT * (int)sizeof(float2));

    fused_kernel<<<GRID, NT, NR * NT * sizeof(float2)>>>(realp, fakep, rmapp,
                                                         (float*)d_out);
}

// round 11
// speedup vs baseline: 2.0769x; 1.1385x over previous
#include <cuda_runtime.h>
#include <cstdint>

#define NR      116
#define NRW     58             // packed count words per thread (2 regions/u32)
#define NT      224            // threads per block (7 warps)
#define NW      7              // warps per block
#define GRID    152            // one CTA per SM (GB300 = 152 SMs)
#define NTOT    (16*3*512*512) // 12,582,912
#define NV4     (NTOT/4)       // 3,145,728
#define ST      4              // cp.async pipeline stages

// Shared layout (dynamic):
//   f32  sumh[NR*NT]               103,936 B   (bank = tid -> conflict-free)
//   u32  cnth[NRW*NT]               51,968 B   (bank = tid -> conflict-free)
//   stages[ST]: {R float4[NT]; F float4[NT]; M int4[NT]}  4 x 10,752 B
#define SUM_BYTES   (NR * NT * 4)
#define CNT_BYTES   (NRW * NT * 4)
#define STG_ARR     (NT * 16)                 // 3584 B per array per stage
#define STG_STRIDE  (3 * STG_ARR)             // 10752 B per stage
#define SMEM_TOTAL  (SUM_BYTES + CNT_BYTES + ST * STG_STRIDE)  // 198,912 B

// Per-block partial (sum, count) per region + last-block ticket.
__device__ float2   g_part[GRID * NR];
__device__ unsigned g_ticket = 0;

__device__ __forceinline__ uint32_t smem_u32(const void* p)
{
    return (uint32_t)__cvta_generic_to_shared(p);
}

// Issue one stage's 3 x 16B cp.async into this thread's private slot, then
// close the group (empty group when invalid keeps group counting uniform).
__device__ __forceinline__ void stage_fill(uint32_t slot,
                                           const float4* Rp, const float4* Fp,
                                           const int4* Mp, int p, bool valid)
{
    if (valid) {
        asm volatile(
            "cp.async.cg.shared.global [%0], [%1], 16;\n\t"
            "cp.async.cg.shared.global [%2], [%3], 16;\n\t"
            "cp.async.cg.shared.global [%4], [%5], 16;\n"
            :: "r"(slot),               "l"(Rp + p),
               "r"(slot + STG_ARR),     "l"(Fp + p),
               "r"(slot + 2 * STG_ARR), "l"(Mp + p)
            : "memory");
    }
    asm volatile("cp.async.commit_group;" ::: "memory");
}

// Accumulate one scalar: f32 sum slot + packed u16x2 count slot.
__device__ __forceinline__ void acc1(float* sum0, unsigned* cnt0,
                                     float x, float y, int r)
{
    sum0[r * NT] += fabsf(x - y);
    cnt0[(r >> 1) * NT] += 1u << ((r & 1) << 4);
}

__device__ __forceinline__ void acc4(float* sum0, unsigned* cnt0,
                                     float4 a, float4 b, int4 m)
{
    acc1(sum0, cnt0, a.x, b.x, m.x);
    acc1(sum0, cnt0, a.y, b.y, m.y);
    acc1(sum0, cnt0, a.z, b.z, m.z);
    acc1(sum0, cnt0, a.w, b.w, m.w);
}

__global__ void __launch_bounds__(NT, 1)
fused_kernel(const float* __restrict__ realp,
             const float* __restrict__ fakep,
             const int*   __restrict__ rmapp,
             float* __restrict__ out)
{
    extern __shared__ unsigned char smem_raw[];
    float*         sumh = (float*)smem_raw;
    unsigned*      cnth = (unsigned*)(smem_raw + SUM_BYTES);
    unsigned char* stg  = smem_raw + SUM_BYTES + CNT_BYTES;

    const int tid  = threadIdx.x;
    const int warp = tid >> 5;
    const int lane = tid & 31;

    // Zero hist region (vectorized, conflict-free).
    {
        float4* h4 = (float4*)smem_raw;
        const int n4 = (SUM_BYTES + CNT_BYTES) / 16;
        for (int k = tid; k < n4; k += NT)
            h4[k] = make_float4(0.f, 0.f, 0.f, 0.f);
    }
    __syncthreads();

    float*    sum0 = sumh + tid;
    unsigned* cnt0 = cnth + tid;

    const float4* __restrict__ R = (const float4*)realp;
    const float4* __restrict__ F = (const float4*)fakep;
    const int4*   __restrict__ M = (const int4*)rmapp;

    const int T = GRID * NT;
    const int p0 = blockIdx.x * NT + tid;
    const uint32_t slot0 = smem_u32(stg) + tid * 16;

    // Prologue: fill ST stages (one commit group each).
    #pragma unroll
    for (int s = 0; s < ST; s++)
        stage_fill(slot0 + s * STG_STRIDE, R, F, M, p0 + s * T,
                   (p0 + s * T) < NV4);

    int pin = p0 + ST * T;     // next vec4 index to fetch
    int s   = 0;

    // Main loop: thread-private stages, no block barriers. wait_group 3
    // guarantees the oldest group (stage s) has landed; refill it, then
    // accumulate. Up to 3 later stages stay in flight during the smem chain.
    #pragma unroll 1
    for (int pc = p0; pc < NV4; pc += T) {
        asm volatile("cp.async.wait_group 3;" ::: "memory");

        const unsigned char* sb = stg + s * STG_STRIDE + tid * 16;
        float4 a = *(const float4*)(sb);
        float4 b = *(const float4*)(sb + STG_ARR);
        int4   m = *(const int4*)(sb + 2 * STG_ARR);

        stage_fill(slot0 + s * STG_STRIDE, R, F, M, pin, pin < NV4);
        pin += T;

        acc4(sum0, cnt0, a, b, m);
        s = (s + 1) & (ST - 1);
    }
    asm volatile("cp.async.wait_all;" ::: "memory");

    __syncthreads();

    // Block reduction: warp w handles regions w, w+7, ... Lanes stride the
    // thread axis (conflict-free), then shfl-combine.
    for (int r = warp; r < NR; r += NW) {
        float    sv = 0.f;
        unsigned cv = 0;
        const int sh = (r & 1) << 4;
        #pragma unroll
        for (int k = 0; k < NT / 32; k++) {
            sv += sumh[r * NT + lane + k * 32];
            cv += (cnth[(r >> 1) * NT + lane + k * 32] >> sh) & 0xFFFFu;
        }
        #pragma unroll
        for (int o = 16; o; o >>= 1) {
            sv += __shfl_xor_sync(0xffffffffu, sv, o);
            cv += __shfl_xor_sync(0xffffffffu, cv, o);
        }
        if (lane == 0)
            g_part[blockIdx.x * NR + r] = make_float2(sv, (float)cv);
    }

    // ---- last-block finalize (threadfence-reduction pattern) ----
    __threadfence();
    __syncthreads();

    __shared__ unsigned is_last;
    if (tid == 0)
        is_last = (atomicAdd(&g_ticket, 1u) == GRID - 1) ? 1u : 0u;
    __syncthreads();
    if (!is_last)
        return;
    __threadfence();

    // Reuse hist smem for the 116-region final reduction.
    float* sh_s = (float*)smem_raw;
    float* sh_m = sh_s + NR;
    __shared__ float sh_max;

    if (tid < NR) {
        float sv = 0.f, cvf = 0.f;
        #pragma unroll 8
        for (int b = 0; b < GRID; b++) {
            float2 v = g_part[b * NR + tid];
            sv  += v.x;
            cvf += v.y;
        }
        sh_s[tid] = sv;
        sh_m[tid] = sv / (cvf + 1e-6f);
    }
    __syncthreads();

    if (tid < 32) {
        float mx = 0.f;   // running max starts at 0 (matches max(0, max_r m_r))
        for (int r = tid; r < NR; r += 32)
            mx = fmaxf(mx, sh_m[r]);
        #pragma unroll
        for (int o = 16; o; o >>= 1)
            mx = fmaxf(mx, __shfl_xor_sync(0xffffffffu, mx, o));
        if (tid == 0) sh_max = mx;
    }
    __syncthreads();

    if (tid < 32) {
        const float inv = 1e-3f / (sh_max + 1e-6f);
        float tot = 0.f;
        for (int r = tid; r < NR; r += 32)
            tot += sh_s[r] * (1.0f + inv * sh_m[r]);
        #pragma unroll
        for (int o = 16; o; o >>= 1)
            tot += __shfl_xor_sync(0xffffffffu, tot, o);
        if (tid == 0) {
            out[0] = tot / (float)NTOT;
            g_ticket = 0;       // reset for deterministic replay
        }
    }
}

extern "C" void kernel_launch(void* const* d_in, const int* in_sizes, int n_in,
                              void* d_out, int out_size)
{
    const float* realp = (const float*)d_in[0];
    const float* fakep = (const float*)d_in[1];
    const int*   rmapp = (const int*)d_in[2];

    cudaFuncSetAttribute(fused_kernel,
                         cudaFuncAttributeMaxDynamicSharedMemorySize,
                         SMEM_TOTAL);

    fused_kernel<<<GRID, NT, SMEM_TOTAL>>>(realp, fakep, rmapp, (float*)d_out);
}